// round 6
// baseline (speedup 1.0000x reference)
#include <cuda_runtime.h>
#include <cuda_bf16.h>
#include <math_constants.h>
#include <cstdint>

// Problem constants
#define B_DIM 1024
#define D_DIM 2048
#define P_DIM 16384
#define TEMP_INV 20.0f      // 1/0.05
#define MOMENTUM 0.2f

// ---------------- device scratch (static: no runtime alloc) ----------------
__device__ float g_logits[(size_t)B_DIM * P_DIM];                 // 64 MB
__device__ int   g_labels[B_DIM];
__device__ __nv_bfloat16 g_Ah[(size_t)B_DIM * D_DIM];             // 4 MB
__device__ __nv_bfloat16 g_Al[(size_t)B_DIM * D_DIM];             // 4 MB
__device__ __nv_bfloat16 g_Sh[(size_t)P_DIM * D_DIM];             // 64 MB
__device__ __nv_bfloat16 g_Sl[(size_t)P_DIM * D_DIM];             // 64 MB

// ---------------- helpers ----------------
__device__ __forceinline__ uint32_t smem_to_u32(const void* p) {
    uint32_t a;
    asm("{ .reg .u64 t; cvta.to.shared.u64 t, %1; cvt.u32.u64 %0, t; }"
        : "=r"(a) : "l"(p));
    return a;
}

__device__ __forceinline__ void ldsm_x4(uint32_t& r0, uint32_t& r1,
                                        uint32_t& r2, uint32_t& r3,
                                        uint32_t addr) {
    asm volatile("ldmatrix.sync.aligned.m8n8.x4.shared.b16 {%0,%1,%2,%3}, [%4];"
                 : "=r"(r0), "=r"(r1), "=r"(r2), "=r"(r3) : "r"(addr));
}

__device__ __forceinline__ void mma_bf16(float* d, const uint32_t* a,
                                         uint32_t b0, uint32_t b1) {
    asm volatile(
        "mma.sync.aligned.m16n8k16.row.col.f32.bf16.bf16.f32 "
        "{%0,%1,%2,%3}, {%4,%5,%6,%7}, {%8,%9}, {%0,%1,%2,%3};"
        : "+f"(d[0]), "+f"(d[1]), "+f"(d[2]), "+f"(d[3])
        : "r"(a[0]), "r"(a[1]), "r"(a[2]), "r"(a[3]), "r"(b0), "r"(b1));
}

__device__ __forceinline__ void cp_async16(uint32_t dst, const void* src) {
    asm volatile("cp.async.cg.shared.global [%0], [%1], 16;"
                 :: "r"(dst), "l"(src));
}

// ---------------------------------------------------------------------------
// Kernel 0: zero loss + ingest labels (int32 OR int64 buffer, auto-detected)
// ---------------------------------------------------------------------------
__global__ void prologue_kernel(const void* __restrict__ raw_labels,
                                float* __restrict__ loss)
{
    if (threadIdx.x == 0) *loss = 0.0f;

    const int* as32 = (const int*)raw_labels;
    __shared__ int is64;
    if (threadIdx.x == 0) {
        int all_hi_zero = 1;
        for (int i = 0; i < 64; ++i)
            if (as32[2 * i + 1] != 0) { all_hi_zero = 0; break; }
        is64 = all_hi_zero;
    }
    __syncthreads();

    if (is64) {
        const long long* as64 = (const long long*)raw_labels;
        for (int i = threadIdx.x; i < B_DIM; i += blockDim.x)
            g_labels[i] = (int)as64[i];
    } else {
        for (int i = threadIdx.x; i < B_DIM; i += blockDim.x)
            g_labels[i] = as32[i];
    }
}

// ---------------------------------------------------------------------------
// Kernel 1a: X fp32 -> bf16 hi/lo split
// ---------------------------------------------------------------------------
__global__ __launch_bounds__(256) void split_kernel(
    const float* __restrict__ src,
    __nv_bfloat16* __restrict__ hi,
    __nv_bfloat16* __restrict__ lo)
{
    size_t i = (size_t)blockIdx.x * 256 + threadIdx.x;   // float4 index
    float4 v = ((const float4*)src)[i];
    __nv_bfloat16 h0 = __float2bfloat16(v.x);
    __nv_bfloat16 h1 = __float2bfloat16(v.y);
    __nv_bfloat16 h2 = __float2bfloat16(v.z);
    __nv_bfloat16 h3 = __float2bfloat16(v.w);
    __nv_bfloat16 l0 = __float2bfloat16(v.x - __bfloat162float(h0));
    __nv_bfloat16 l1 = __float2bfloat16(v.y - __bfloat162float(h1));
    __nv_bfloat16 l2 = __float2bfloat16(v.z - __bfloat162float(h2));
    __nv_bfloat16 l3 = __float2bfloat16(v.w - __bfloat162float(h3));
    ushort4 ph = make_ushort4(*(unsigned short*)&h0, *(unsigned short*)&h1,
                              *(unsigned short*)&h2, *(unsigned short*)&h3);
    ushort4 pl = make_ushort4(*(unsigned short*)&l0, *(unsigned short*)&l1,
                              *(unsigned short*)&l2, *(unsigned short*)&l3);
    ((ushort4*)hi)[i] = ph;
    ((ushort4*)lo)[i] = pl;
}

// ---------------------------------------------------------------------------
// Kernel 1b: S split + copy to output (saves a separate 128MB read)
// outS is 4B-aligned only (d_out+1) -> scalar stores
// ---------------------------------------------------------------------------
__global__ __launch_bounds__(256) void split_copy_kernel(
    const float* __restrict__ src,
    __nv_bfloat16* __restrict__ hi,
    __nv_bfloat16* __restrict__ lo,
    float* __restrict__ outS)
{
    size_t i = (size_t)blockIdx.x * 256 + threadIdx.x;   // float4 index
    float4 v = ((const float4*)src)[i];
    __nv_bfloat16 h0 = __float2bfloat16(v.x);
    __nv_bfloat16 h1 = __float2bfloat16(v.y);
    __nv_bfloat16 h2 = __float2bfloat16(v.z);
    __nv_bfloat16 h3 = __float2bfloat16(v.w);
    __nv_bfloat16 l0 = __float2bfloat16(v.x - __bfloat162float(h0));
    __nv_bfloat16 l1 = __float2bfloat16(v.y - __bfloat162float(h1));
    __nv_bfloat16 l2 = __float2bfloat16(v.z - __bfloat162float(h2));
    __nv_bfloat16 l3 = __float2bfloat16(v.w - __bfloat162float(h3));
    ushort4 ph = make_ushort4(*(unsigned short*)&h0, *(unsigned short*)&h1,
                              *(unsigned short*)&h2, *(unsigned short*)&h3);
    ushort4 pl = make_ushort4(*(unsigned short*)&l0, *(unsigned short*)&l1,
                              *(unsigned short*)&l2, *(unsigned short*)&l3);
    ((ushort4*)hi)[i] = ph;
    ((ushort4*)lo)[i] = pl;
    float* o = outS + i * 4;
    o[0] = v.x; o[1] = v.y; o[2] = v.z; o[3] = v.w;
}

// ---------------------------------------------------------------------------
// Kernel 2: classic-tensor-core GEMM  logits = 20 * (xh·sh + xh·sl + xl·sh)
// CTA 128x128, BK=32, 8 warps (warp tile 32x64), mma.m16n8k16 bf16,
// 4-stage cp.async pipeline (dynamic SMEM 80KB), padded stride 80B.
// ---------------------------------------------------------------------------
#define STAGE_BYTES 10240      // 128 rows x 80 B
#define B_OFF       40960      // 4 A stages then 4 B stages
#define SM_TOTAL    81920
#define N_CHUNKS    192        // 3 passes x (2048 / 32)

__global__ __launch_bounds__(256, 2) void gemm_mma_kernel()
{
    extern __shared__ __nv_bfloat16 smem[];
    const uint32_t sbase = smem_to_u32(smem);

    const int tid  = threadIdx.x;
    const int lane = tid & 31;
    const int wid  = tid >> 5;
    const int wm   = wid & 3;        // 4 m-warps (32 rows each)
    const int wn   = wid >> 2;       // 2 n-warps (64 cols each)
    const int m0   = blockIdx.x * 128;
    const int n0   = blockIdx.y * 128;

    // cp.async chunk mapping: 512 x 16B per tile; thread handles chunks tid, tid+256
    const int c0r = tid >> 2, c0c = tid & 3;           // rows 0..63
    const uint32_t a_sm0 = (uint32_t)(c0r * 80 + c0c * 16);
    const uint32_t a_sm1 = a_sm0 + 64 * 80;            // rows 64..127

    // ldmatrix lane-invariant offsets
    const uint32_t a_lds = (uint32_t)((wm * 32 + (lane & 15)) * 80 + (lane >> 4) * 16);
    const uint32_t b_lds = (uint32_t)((wn * 64 + (lane & 7) + ((lane >> 3) & 1) * 8) * 80
                                      + (lane >> 4) * 16);

    // per-thread global element offsets (seg-independent)
    const size_t offA0 = (size_t)(m0 + c0r) * D_DIM + c0c * 8;
    const size_t offA1 = offA0 + (size_t)64 * D_DIM;
    const size_t offB0 = (size_t)(n0 + c0r) * D_DIM + c0c * 8;
    const size_t offB1 = offB0 + (size_t)64 * D_DIM;

    // issue pointers, advanced 32 elems per chunk, reset at segment boundary
    const __nv_bfloat16* ipA0 = g_Ah + offA0;
    const __nv_bfloat16* ipA1 = g_Ah + offA1;
    const __nv_bfloat16* ipB0 = g_Sh + offB0;
    const __nv_bfloat16* ipB1 = g_Sh + offB1;

    float d[2][8][4];
#pragma unroll
    for (int t = 0; t < 2; ++t)
#pragma unroll
        for (int j = 0; j < 8; ++j)
#pragma unroll
            for (int k = 0; k < 4; ++k) d[t][j][k] = 0.0f;

    auto issue = [&](int ci) {
        const uint32_t ab = sbase + (uint32_t)(ci & 3) * STAGE_BYTES;
        const uint32_t bb = ab + B_OFF;
        cp_async16(ab + a_sm0, ipA0);
        cp_async16(ab + a_sm1, ipA1);
        cp_async16(bb + a_sm0, ipB0);
        cp_async16(bb + a_sm1, ipB1);
        asm volatile("cp.async.commit_group;");
        ipA0 += 32; ipA1 += 32; ipB0 += 32; ipB1 += 32;
        if (((ci + 1) & 63) == 0) {
            const int sg = (ci + 1) >> 6;     // 1 or 2 (3 = past end, ignore)
            if (sg == 1) {                    // xh * sl
                ipA0 = g_Ah + offA0; ipA1 = g_Ah + offA1;
                ipB0 = g_Sl + offB0; ipB1 = g_Sl + offB1;
            } else if (sg == 2) {             // xl * sh
                ipA0 = g_Al + offA0; ipA1 = g_Al + offA1;
                ipB0 = g_Sh + offB0; ipB1 = g_Sh + offB1;
            }
        }
    };

    issue(0); issue(1); issue(2);

    for (int c = 0; c < N_CHUNKS; ++c) {
        if (c < N_CHUNKS - 2)       asm volatile("cp.async.wait_group 2;");
        else if (c == N_CHUNKS - 2) asm volatile("cp.async.wait_group 1;");
        else                        asm volatile("cp.async.wait_group 0;");
        __syncthreads();

        if (c + 3 < N_CHUNKS) issue(c + 3);

        const uint32_t abase = sbase + (uint32_t)(c & 3) * STAGE_BYTES;
        const uint32_t bbase = abase + B_OFF;

#pragma unroll
        for (int ks = 0; ks < 2; ++ks) {
            uint32_t a[2][4];
#pragma unroll
            for (int t = 0; t < 2; ++t)
                ldsm_x4(a[t][0], a[t][1], a[t][2], a[t][3],
                        abase + a_lds + t * 1280 + ks * 32);
            uint32_t b[4][4];
#pragma unroll
            for (int j = 0; j < 4; ++j)
                ldsm_x4(b[j][0], b[j][1], b[j][2], b[j][3],
                        bbase + b_lds + j * 1280 + ks * 32);
#pragma unroll
            for (int t = 0; t < 2; ++t)
#pragma unroll
                for (int j = 0; j < 4; ++j) {
                    mma_bf16(d[t][2 * j + 0], a[t], b[j][0], b[j][2]);
                    mma_bf16(d[t][2 * j + 1], a[t], b[j][1], b[j][3]);
                }
        }
    }

    // epilogue: scale by 20, store fp32 logits
#pragma unroll
    for (int t = 0; t < 2; ++t) {
        const int mrow = m0 + wm * 32 + t * 16 + (lane >> 2);
#pragma unroll
        for (int j = 0; j < 8; ++j) {
            const int col = n0 + wn * 64 + j * 8 + (lane & 3) * 2;
            float2 lo2 = make_float2(d[t][j][0] * TEMP_INV, d[t][j][1] * TEMP_INV);
            float2 hi2 = make_float2(d[t][j][2] * TEMP_INV, d[t][j][3] * TEMP_INV);
            *(float2*)(g_logits + (size_t)mrow * P_DIM + col) = lo2;
            *(float2*)(g_logits + (size_t)(mrow + 8) * P_DIM + col) = hi2;
        }
    }
}

// ---------------------------------------------------------------------------
// Kernel 3: per-row logsumexp + NLL contribution (one block per batch row)
// ---------------------------------------------------------------------------
__global__ __launch_bounds__(256) void lse_loss_kernel(float* __restrict__ loss)
{
    const int b = blockIdx.x;
    const int tid = threadIdx.x;
    const float* row = g_logits + (size_t)b * P_DIM;
    __shared__ float sh[256];

    float mx = -CUDART_INF_F;
    for (int i = tid; i < P_DIM; i += 256) mx = fmaxf(mx, row[i]);
    sh[tid] = mx; __syncthreads();
    for (int s = 128; s > 0; s >>= 1) {
        if (tid < s) sh[tid] = fmaxf(sh[tid], sh[tid + s]);
        __syncthreads();
    }
    const float m = sh[0];
    __syncthreads();

    float acc = 0.0f;
    for (int i = tid; i < P_DIM; i += 256) acc += __expf(row[i] - m);
    sh[tid] = acc; __syncthreads();
    for (int s = 128; s > 0; s >>= 1) {
        if (tid < s) sh[tid] += sh[tid + s];
        __syncthreads();
    }

    if (tid == 0) {
        float lse = m + logf(sh[0]);
        float tgt = row[g_labels[b]];
        atomicAdd(loss, (lse - tgt) * (1.0f / (float)B_DIM));
    }
}

// ---------------------------------------------------------------------------
// Kernel 4: sequential momentum-EMA scatter + renorm (first-occurrence blocks
// replay the full duplicate chain, matching the reference scan semantics)
// ---------------------------------------------------------------------------
__global__ __launch_bounds__(256) void ema_update_kernel(
    const float* __restrict__ X,
    const float* __restrict__ S,
    float* __restrict__ outS)
{
    const int b = blockIdx.x;
    const int lab = g_labels[b];

    for (int b2 = 0; b2 < b; ++b2)
        if (g_labels[b2] == lab) return;

    const int tid = threadIdx.x;
    __shared__ float sh[256];

    float r[8];
    const float* srow = S + (size_t)lab * D_DIM;
#pragma unroll
    for (int i = 0; i < 8; ++i) r[i] = srow[tid + i * 256];

    for (int b2 = b; b2 < B_DIM; ++b2) {
        if (g_labels[b2] != lab) continue;
        const float* x = X + (size_t)b2 * D_DIM;
        float ss = 0.0f;
#pragma unroll
        for (int i = 0; i < 8; ++i) {
            r[i] = MOMENTUM * r[i] + (1.0f - MOMENTUM) * x[tid + i * 256];
            ss = fmaf(r[i], r[i], ss);
        }
        sh[tid] = ss; __syncthreads();
        for (int s = 128; s > 0; s >>= 1) {
            if (tid < s) sh[tid] += sh[tid + s];
            __syncthreads();
        }
        float inv = 1.0f / sqrtf(sh[0]);
        __syncthreads();
#pragma unroll
        for (int i = 0; i < 8; ++i) r[i] *= inv;
    }

    float* orow = outS + (size_t)lab * D_DIM;
#pragma unroll
    for (int i = 0; i < 8; ++i) orow[tid + i * 256] = r[i];
}

// ---------------------------------------------------------------------------
extern "C" void kernel_launch(void* const* d_in, const int* in_sizes, int n_in,
                              void* d_out, int out_size)
{
    const float* X      = (const float*)d_in[0];
    const float* S      = (const float*)d_in[1];
    const void*  alabel = d_in[4];

    float* out  = (float*)d_out;
    float* loss = out;
    float* outS = out + 1;

    static __nv_bfloat16 *Ah_p = nullptr, *Al_p = nullptr, *Sh_p = nullptr, *Sl_p = nullptr;
    if (!Ah_p) {
        cudaGetSymbolAddress((void**)&Ah_p, g_Ah);
        cudaGetSymbolAddress((void**)&Al_p, g_Al);
        cudaGetSymbolAddress((void**)&Sh_p, g_Sh);
        cudaGetSymbolAddress((void**)&Sl_p, g_Sl);
        cudaFuncSetAttribute(gemm_mma_kernel,
                             cudaFuncAttributeMaxDynamicSharedMemorySize, SM_TOTAL);
    }

    prologue_kernel<<<1, 256>>>(alabel, loss);

    split_kernel<<<(B_DIM * D_DIM) / 1024, 256>>>(X, Ah_p, Al_p);
    split_copy_kernel<<<(P_DIM * D_DIM) / 1024, 256>>>(S, Sh_p, Sl_p, outS);

    dim3 ggrid(B_DIM / 128, P_DIM / 128);   // 8 x 128 (m-major waves)
    gemm_mma_kernel<<<ggrid, 256, SM_TOTAL>>>();

    lse_loss_kernel<<<B_DIM, 256>>>(loss);

    ema_update_kernel<<<B_DIM, 256>>>(X, S, outS);
}

// round 7
// speedup vs baseline: 1.4710x; 1.4710x over previous
#include <cuda_runtime.h>
#include <cuda_bf16.h>
#include <math_constants.h>
#include <cstdint>

// Problem constants
#define B_DIM 1024
#define D_DIM 2048
#define P_DIM 16384
#define TEMP_INV 20.0f      // 1/0.05
#define MOMENTUM 0.2f

// ---------------- device scratch (static: no runtime alloc) ----------------
__device__ float g_logits[(size_t)B_DIM * P_DIM];                 // 64 MB
__device__ int   g_labels[B_DIM];
__device__ __nv_bfloat16 g_Ah[(size_t)B_DIM * D_DIM];             // 4 MB
__device__ __nv_bfloat16 g_Al[(size_t)B_DIM * D_DIM];             // 4 MB
__device__ __nv_bfloat16 g_Sh[(size_t)P_DIM * D_DIM];             // 64 MB
__device__ __nv_bfloat16 g_Sl[(size_t)P_DIM * D_DIM];             // 64 MB

// ---------------- helpers ----------------
__device__ __forceinline__ uint32_t smem_to_u32(const void* p) {
    uint32_t a;
    asm("{ .reg .u64 t; cvta.to.shared.u64 t, %1; cvt.u32.u64 %0, t; }"
        : "=r"(a) : "l"(p));
    return a;
}

__device__ __forceinline__ void ldsm_x4(uint32_t& r0, uint32_t& r1,
                                        uint32_t& r2, uint32_t& r3,
                                        uint32_t addr) {
    asm volatile("ldmatrix.sync.aligned.m8n8.x4.shared.b16 {%0,%1,%2,%3}, [%4];"
                 : "=r"(r0), "=r"(r1), "=r"(r2), "=r"(r3) : "r"(addr));
}

__device__ __forceinline__ void mma_bf16(float* d, const uint32_t* a,
                                         uint32_t b0, uint32_t b1) {
    asm volatile(
        "mma.sync.aligned.m16n8k16.row.col.f32.bf16.bf16.f32 "
        "{%0,%1,%2,%3}, {%4,%5,%6,%7}, {%8,%9}, {%0,%1,%2,%3};"
        : "+f"(d[0]), "+f"(d[1]), "+f"(d[2]), "+f"(d[3])
        : "r"(a[0]), "r"(a[1]), "r"(a[2]), "r"(a[3]), "r"(b0), "r"(b1));
}

__device__ __forceinline__ void cp_async16(uint32_t dst, const void* src) {
    asm volatile("cp.async.cg.shared.global [%0], [%1], 16;"
                 :: "r"(dst), "l"(src));
}

// ---------------------------------------------------------------------------
// Kernel 0: zero loss + ingest labels (int32 OR int64 buffer, auto-detected)
// ---------------------------------------------------------------------------
__global__ void prologue_kernel(const void* __restrict__ raw_labels,
                                float* __restrict__ loss)
{
    if (threadIdx.x == 0) *loss = 0.0f;

    const int* as32 = (const int*)raw_labels;
    __shared__ int is64;
    if (threadIdx.x == 0) {
        int all_hi_zero = 1;
        for (int i = 0; i < 64; ++i)
            if (as32[2 * i + 1] != 0) { all_hi_zero = 0; break; }
        is64 = all_hi_zero;
    }
    __syncthreads();

    if (is64) {
        const long long* as64 = (const long long*)raw_labels;
        for (int i = threadIdx.x; i < B_DIM; i += blockDim.x)
            g_labels[i] = (int)as64[i];
    } else {
        for (int i = threadIdx.x; i < B_DIM; i += blockDim.x)
            g_labels[i] = as32[i];
    }
}

// ---------------------------------------------------------------------------
// Kernel 1a: X fp32 -> bf16 hi/lo split
// ---------------------------------------------------------------------------
__global__ __launch_bounds__(256) void split_kernel(
    const float* __restrict__ src,
    __nv_bfloat16* __restrict__ hi,
    __nv_bfloat16* __restrict__ lo)
{
    size_t i = (size_t)blockIdx.x * 256 + threadIdx.x;   // float4 index
    float4 v = ((const float4*)src)[i];
    __nv_bfloat16 h0 = __float2bfloat16(v.x);
    __nv_bfloat16 h1 = __float2bfloat16(v.y);
    __nv_bfloat16 h2 = __float2bfloat16(v.z);
    __nv_bfloat16 h3 = __float2bfloat16(v.w);
    __nv_bfloat16 l0 = __float2bfloat16(v.x - __bfloat162float(h0));
    __nv_bfloat16 l1 = __float2bfloat16(v.y - __bfloat162float(h1));
    __nv_bfloat16 l2 = __float2bfloat16(v.z - __bfloat162float(h2));
    __nv_bfloat16 l3 = __float2bfloat16(v.w - __bfloat162float(h3));
    ushort4 ph = make_ushort4(*(unsigned short*)&h0, *(unsigned short*)&h1,
                              *(unsigned short*)&h2, *(unsigned short*)&h3);
    ushort4 pl = make_ushort4(*(unsigned short*)&l0, *(unsigned short*)&l1,
                              *(unsigned short*)&l2, *(unsigned short*)&l3);
    ((ushort4*)hi)[i] = ph;
    ((ushort4*)lo)[i] = pl;
}

// ---------------------------------------------------------------------------
// Kernel 1b: S split + copy to output (saves a separate 128MB read)
// outS is 4B-aligned only (d_out+1) -> scalar stores
// ---------------------------------------------------------------------------
__global__ __launch_bounds__(256) void split_copy_kernel(
    const float* __restrict__ src,
    __nv_bfloat16* __restrict__ hi,
    __nv_bfloat16* __restrict__ lo,
    float* __restrict__ outS)
{
    size_t i = (size_t)blockIdx.x * 256 + threadIdx.x;   // float4 index
    float4 v = ((const float4*)src)[i];
    __nv_bfloat16 h0 = __float2bfloat16(v.x);
    __nv_bfloat16 h1 = __float2bfloat16(v.y);
    __nv_bfloat16 h2 = __float2bfloat16(v.z);
    __nv_bfloat16 h3 = __float2bfloat16(v.w);
    __nv_bfloat16 l0 = __float2bfloat16(v.x - __bfloat162float(h0));
    __nv_bfloat16 l1 = __float2bfloat16(v.y - __bfloat162float(h1));
    __nv_bfloat16 l2 = __float2bfloat16(v.z - __bfloat162float(h2));
    __nv_bfloat16 l3 = __float2bfloat16(v.w - __bfloat162float(h3));
    ushort4 ph = make_ushort4(*(unsigned short*)&h0, *(unsigned short*)&h1,
                              *(unsigned short*)&h2, *(unsigned short*)&h3);
    ushort4 pl = make_ushort4(*(unsigned short*)&l0, *(unsigned short*)&l1,
                              *(unsigned short*)&l2, *(unsigned short*)&l3);
    ((ushort4*)hi)[i] = ph;
    ((ushort4*)lo)[i] = pl;
    float* o = outS + i * 4;
    o[0] = v.x; o[1] = v.y; o[2] = v.z; o[3] = v.w;
}

// ---------------------------------------------------------------------------
// Kernel 2: classic-tensor-core GEMM  logits = 20 * (xh·sh + xh·sl + xl·sh)
// CTA 128x128, BK=32, 8 warps (warp tile 32x64), mma.m16n8k16 bf16.
// R5 loop skeleton (issue-before-wait, leading+trailing barriers) with
// pipeline depth 4 (dynamic SMEM, 80KB, 2 CTAs/SM).
// ---------------------------------------------------------------------------
#define STAGE_BYTES 10240      // 128 rows x 80 B
#define B_OFF       40960      // 4 A stages then 4 B stages
#define SM_TOTAL    81920
#define N_CHUNKS    192        // 3 passes x (2048 / 32)

__global__ __launch_bounds__(256, 2) void gemm_mma_kernel()
{
    extern __shared__ __nv_bfloat16 smem[];
    const uint32_t sbase = smem_to_u32(smem);

    const int tid  = threadIdx.x;
    const int lane = tid & 31;
    const int wid  = tid >> 5;
    const int wm   = wid & 3;        // 4 m-warps (32 rows each)
    const int wn   = wid >> 2;       // 2 n-warps (64 cols each)
    const int m0   = blockIdx.x * 128;
    const int n0   = blockIdx.y * 128;

    // cp.async chunk mapping: 512 x 16B per tile; thread handles rows r, r+64
    const int c0r = tid >> 2, c0c = tid & 3;
    const uint32_t a_sm0 = (uint32_t)(c0r * 80 + c0c * 16);
    const uint32_t a_sm1 = a_sm0 + 64 * 80;

    // ldmatrix lane-invariant offsets
    const uint32_t a_lds = (uint32_t)((wm * 32 + (lane & 15)) * 80 + (lane >> 4) * 16);
    const uint32_t b_lds = (uint32_t)((wn * 64 + (lane & 7) + ((lane >> 3) & 1) * 8) * 80
                                      + (lane >> 4) * 16);

    float d[2][8][4];
#pragma unroll
    for (int t = 0; t < 2; ++t)
#pragma unroll
        for (int j = 0; j < 8; ++j)
#pragma unroll
            for (int k = 0; k < 4; ++k) d[t][j][k] = 0.0f;

    // R5-style issue: recompute addresses, segment select by chunk index
    auto issue = [&](int c) {
        const __nv_bfloat16 *pa, *pb;
        const int seg = c >> 6;
        if (seg == 0)      { pa = g_Ah; pb = g_Sh; }
        else if (seg == 1) { pa = g_Ah; pb = g_Sl; }
        else               { pa = g_Al; pb = g_Sh; }
        const int kk = (c & 63) << 5;   // *32
        const uint32_t ab = sbase + (uint32_t)(c & 3) * STAGE_BYTES;
        const uint32_t bb = ab + B_OFF;
        cp_async16(ab + a_sm0, pa + (size_t)(m0 + c0r) * D_DIM + kk + c0c * 8);
        cp_async16(ab + a_sm1, pa + (size_t)(m0 + 64 + c0r) * D_DIM + kk + c0c * 8);
        cp_async16(bb + a_sm0, pb + (size_t)(n0 + c0r) * D_DIM + kk + c0c * 8);
        cp_async16(bb + a_sm1, pb + (size_t)(n0 + 64 + c0r) * D_DIM + kk + c0c * 8);
        asm volatile("cp.async.commit_group;");
    };

    issue(0); issue(1); issue(2);

    for (int c = 0; c < N_CHUNKS; ++c) {
        // prefetch FIRST (overlaps the wait), then wait for group c
        if (c + 3 < N_CHUNKS) {
            issue(c + 3);
            asm volatile("cp.async.wait_group 3;");
        } else if (c + 1 < N_CHUNKS) {
            asm volatile("cp.async.wait_group 1;");  // covers tail conservatively
        } else {
            asm volatile("cp.async.wait_group 0;");
        }
        __syncthreads();

        const uint32_t abase = sbase + (uint32_t)(c & 3) * STAGE_BYTES;
        const uint32_t bbase = abase + B_OFF;

#pragma unroll
        for (int ks = 0; ks < 2; ++ks) {
            uint32_t a[2][4];
#pragma unroll
            for (int t = 0; t < 2; ++t)
                ldsm_x4(a[t][0], a[t][1], a[t][2], a[t][3],
                        abase + a_lds + t * 1280 + ks * 32);
            uint32_t b[4][4];
#pragma unroll
            for (int j = 0; j < 4; ++j)
                ldsm_x4(b[j][0], b[j][1], b[j][2], b[j][3],
                        bbase + b_lds + j * 1280 + ks * 32);
#pragma unroll
            for (int t = 0; t < 2; ++t)
#pragma unroll
                for (int j = 0; j < 4; ++j) {
                    mma_bf16(d[t][2 * j + 0], a[t], b[j][0], b[j][2]);
                    mma_bf16(d[t][2 * j + 1], a[t], b[j][1], b[j][3]);
                }
        }
        __syncthreads();   // trailing barrier: makes next issue into stage (c)&3 safe
    }

    // epilogue: scale by 20, store fp32 logits
#pragma unroll
    for (int t = 0; t < 2; ++t) {
        const int mrow = m0 + wm * 32 + t * 16 + (lane >> 2);
#pragma unroll
        for (int j = 0; j < 8; ++j) {
            const int col = n0 + wn * 64 + j * 8 + (lane & 3) * 2;
            float2 lo2 = make_float2(d[t][j][0] * TEMP_INV, d[t][j][1] * TEMP_INV);
            float2 hi2 = make_float2(d[t][j][2] * TEMP_INV, d[t][j][3] * TEMP_INV);
            *(float2*)(g_logits + (size_t)mrow * P_DIM + col) = lo2;
            *(float2*)(g_logits + (size_t)(mrow + 8) * P_DIM + col) = hi2;
        }
    }
}

// ---------------------------------------------------------------------------
// Kernel 3: per-row logsumexp + NLL contribution (one block per batch row)
// ---------------------------------------------------------------------------
__global__ __launch_bounds__(256) void lse_loss_kernel(float* __restrict__ loss)
{
    const int b = blockIdx.x;
    const int tid = threadIdx.x;
    const float* row = g_logits + (size_t)b * P_DIM;
    __shared__ float sh[256];

    float mx = -CUDART_INF_F;
    for (int i = tid; i < P_DIM; i += 256) mx = fmaxf(mx, row[i]);
    sh[tid] = mx; __syncthreads();
    for (int s = 128; s > 0; s >>= 1) {
        if (tid < s) sh[tid] = fmaxf(sh[tid], sh[tid + s]);
        __syncthreads();
    }
    const float m = sh[0];
    __syncthreads();

    float acc = 0.0f;
    for (int i = tid; i < P_DIM; i += 256) acc += __expf(row[i] - m);
    sh[tid] = acc; __syncthreads();
    for (int s = 128; s > 0; s >>= 1) {
        if (tid < s) sh[tid] += sh[tid + s];
        __syncthreads();
    }

    if (tid == 0) {
        float lse = m + logf(sh[0]);
        float tgt = row[g_labels[b]];
        atomicAdd(loss, (lse - tgt) * (1.0f / (float)B_DIM));
    }
}

// ---------------------------------------------------------------------------
// Kernel 4: sequential momentum-EMA scatter + renorm (first-occurrence blocks
// replay the full duplicate chain, matching the reference scan semantics)
// ---------------------------------------------------------------------------
__global__ __launch_bounds__(256) void ema_update_kernel(
    const float* __restrict__ X,
    const float* __restrict__ S,
    float* __restrict__ outS)
{
    const int b = blockIdx.x;
    const int lab = g_labels[b];

    for (int b2 = 0; b2 < b; ++b2)
        if (g_labels[b2] == lab) return;

    const int tid = threadIdx.x;
    __shared__ float sh[256];

    float r[8];
    const float* srow = S + (size_t)lab * D_DIM;
#pragma unroll
    for (int i = 0; i < 8; ++i) r[i] = srow[tid + i * 256];

    for (int b2 = b; b2 < B_DIM; ++b2) {
        if (g_labels[b2] != lab) continue;
        const float* x = X + (size_t)b2 * D_DIM;
        float ss = 0.0f;
#pragma unroll
        for (int i = 0; i < 8; ++i) {
            r[i] = MOMENTUM * r[i] + (1.0f - MOMENTUM) * x[tid + i * 256];
            ss = fmaf(r[i], r[i], ss);
        }
        sh[tid] = ss; __syncthreads();
        for (int s = 128; s > 0; s >>= 1) {
            if (tid < s) sh[tid] += sh[tid + s];
            __syncthreads();
        }
        float inv = 1.0f / sqrtf(sh[0]);
        __syncthreads();
#pragma unroll
        for (int i = 0; i < 8; ++i) r[i] *= inv;
    }

    float* orow = outS + (size_t)lab * D_DIM;
#pragma unroll
    for (int i = 0; i < 8; ++i) orow[tid + i * 256] = r[i];
}

// ---------------------------------------------------------------------------
extern "C" void kernel_launch(void* const* d_in, const int* in_sizes, int n_in,
                              void* d_out, int out_size)
{
    const float* X      = (const float*)d_in[0];
    const float* S      = (const float*)d_in[1];
    const void*  alabel = d_in[4];

    float* out  = (float*)d_out;
    float* loss = out;
    float* outS = out + 1;

    static __nv_bfloat16 *Ah_p = nullptr, *Al_p = nullptr, *Sh_p = nullptr, *Sl_p = nullptr;
    if (!Ah_p) {
        cudaGetSymbolAddress((void**)&Ah_p, g_Ah);
        cudaGetSymbolAddress((void**)&Al_p, g_Al);
        cudaGetSymbolAddress((void**)&Sh_p, g_Sh);
        cudaGetSymbolAddress((void**)&Sl_p, g_Sl);
        cudaFuncSetAttribute(gemm_mma_kernel,
                             cudaFuncAttributeMaxDynamicSharedMemorySize, SM_TOTAL);
    }

    prologue_kernel<<<1, 256>>>(alabel, loss);

    split_kernel<<<(B_DIM * D_DIM) / 1024, 256>>>(X, Ah_p, Al_p);
    split_copy_kernel<<<(P_DIM * D_DIM) / 1024, 256>>>(S, Sh_p, Sl_p, outS);

    dim3 ggrid(B_DIM / 128, P_DIM / 128);   // 8 x 128 (m-major waves)
    gemm_mma_kernel<<<ggrid, 256, SM_TOTAL>>>();

    lse_loss_kernel<<<B_DIM, 256>>>(loss);

    ema_update_kernel<<<B_DIM, 256>>>(X, S, outS);
}

// round 9
// speedup vs baseline: 1.6224x; 1.1029x over previous
#include <cuda_runtime.h>
#include <cuda_bf16.h>
#include <math_constants.h>
#include <cstdint>

// Problem constants
#define B_DIM 1024
#define D_DIM 2048
#define P_DIM 16384
#define TEMP_INV 20.0f      // 1/0.05
#define MOMENTUM 0.2f

// ---------------- device scratch (static: no runtime alloc) ----------------
__device__ float g_logits[(size_t)B_DIM * P_DIM];                 // 64 MB
__device__ int   g_labels[B_DIM];
__device__ __nv_bfloat16 g_Ah[(size_t)B_DIM * D_DIM];             // 4 MB
__device__ __nv_bfloat16 g_Al[(size_t)B_DIM * D_DIM];             // 4 MB
__device__ __nv_bfloat16 g_Sh[(size_t)P_DIM * D_DIM];             // 64 MB
__device__ __nv_bfloat16 g_Sl[(size_t)P_DIM * D_DIM];             // 64 MB

// ---------------- helpers ----------------
__device__ __forceinline__ uint32_t smem_to_u32(const void* p) {
    uint32_t a;
    asm("{ .reg .u64 t; cvta.to.shared.u64 t, %1; cvt.u32.u64 %0, t; }"
        : "=r"(a) : "l"(p));
    return a;
}

__device__ __forceinline__ void ldsm_x4(uint32_t& r0, uint32_t& r1,
                                        uint32_t& r2, uint32_t& r3,
                                        uint32_t addr) {
    asm volatile("ldmatrix.sync.aligned.m8n8.x4.shared.b16 {%0,%1,%2,%3}, [%4];"
                 : "=r"(r0), "=r"(r1), "=r"(r2), "=r"(r3) : "r"(addr));
}

__device__ __forceinline__ void mma_bf16(float* d, const uint32_t* a,
                                         uint32_t b0, uint32_t b1) {
    asm volatile(
        "mma.sync.aligned.m16n8k16.row.col.f32.bf16.bf16.f32 "
        "{%0,%1,%2,%3}, {%4,%5,%6,%7}, {%8,%9}, {%0,%1,%2,%3};"
        : "+f"(d[0]), "+f"(d[1]), "+f"(d[2]), "+f"(d[3])
        : "r"(a[0]), "r"(a[1]), "r"(a[2]), "r"(a[3]), "r"(b0), "r"(b1));
}

__device__ __forceinline__ void cp_async16(uint32_t dst, const void* src) {
    asm volatile("cp.async.cg.shared.global [%0], [%1], 16;"
                 :: "r"(dst), "l"(src));
}

// ---------------------------------------------------------------------------
// Kernel 0: zero loss + ingest labels (int32 OR int64 buffer, auto-detected)
// ---------------------------------------------------------------------------
__global__ void prologue_kernel(const void* __restrict__ raw_labels,
                                float* __restrict__ loss)
{
    if (threadIdx.x == 0) *loss = 0.0f;

    const int* as32 = (const int*)raw_labels;
    __shared__ int is64;
    if (threadIdx.x == 0) {
        int all_hi_zero = 1;
        for (int i = 0; i < 64; ++i)
            if (as32[2 * i + 1] != 0) { all_hi_zero = 0; break; }
        is64 = all_hi_zero;
    }
    __syncthreads();

    if (is64) {
        const long long* as64 = (const long long*)raw_labels;
        for (int i = threadIdx.x; i < B_DIM; i += blockDim.x)
            g_labels[i] = (int)as64[i];
    } else {
        for (int i = threadIdx.x; i < B_DIM; i += blockDim.x)
            g_labels[i] = as32[i];
    }
}

// ---------------------------------------------------------------------------
// Kernel 1a: X fp32 -> bf16 hi/lo split
// ---------------------------------------------------------------------------
__global__ __launch_bounds__(256) void split_kernel(
    const float* __restrict__ src,
    __nv_bfloat16* __restrict__ hi,
    __nv_bfloat16* __restrict__ lo)
{
    size_t i = (size_t)blockIdx.x * 256 + threadIdx.x;   // float4 index
    float4 v = ((const float4*)src)[i];
    __nv_bfloat16 h0 = __float2bfloat16(v.x);
    __nv_bfloat16 h1 = __float2bfloat16(v.y);
    __nv_bfloat16 h2 = __float2bfloat16(v.z);
    __nv_bfloat16 h3 = __float2bfloat16(v.w);
    __nv_bfloat16 l0 = __float2bfloat16(v.x - __bfloat162float(h0));
    __nv_bfloat16 l1 = __float2bfloat16(v.y - __bfloat162float(h1));
    __nv_bfloat16 l2 = __float2bfloat16(v.z - __bfloat162float(h2));
    __nv_bfloat16 l3 = __float2bfloat16(v.w - __bfloat162float(h3));
    ushort4 ph = make_ushort4(*(unsigned short*)&h0, *(unsigned short*)&h1,
                              *(unsigned short*)&h2, *(unsigned short*)&h3);
    ushort4 pl = make_ushort4(*(unsigned short*)&l0, *(unsigned short*)&l1,
                              *(unsigned short*)&l2, *(unsigned short*)&l3);
    ((ushort4*)hi)[i] = ph;
    ((ushort4*)lo)[i] = pl;
}

// ---------------------------------------------------------------------------
// Kernel 1b: S split + copy to output (saves a separate 128MB read)
// outS is 4B-aligned only (d_out+1) -> scalar stores
// ---------------------------------------------------------------------------
__global__ __launch_bounds__(256) void split_copy_kernel(
    const float* __restrict__ src,
    __nv_bfloat16* __restrict__ hi,
    __nv_bfloat16* __restrict__ lo,
    float* __restrict__ outS)
{
    size_t i = (size_t)blockIdx.x * 256 + threadIdx.x;   // float4 index
    float4 v = ((const float4*)src)[i];
    __nv_bfloat16 h0 = __float2bfloat16(v.x);
    __nv_bfloat16 h1 = __float2bfloat16(v.y);
    __nv_bfloat16 h2 = __float2bfloat16(v.z);
    __nv_bfloat16 h3 = __float2bfloat16(v.w);
    __nv_bfloat16 l0 = __float2bfloat16(v.x - __bfloat162float(h0));
    __nv_bfloat16 l1 = __float2bfloat16(v.y - __bfloat162float(h1));
    __nv_bfloat16 l2 = __float2bfloat16(v.z - __bfloat162float(h2));
    __nv_bfloat16 l3 = __float2bfloat16(v.w - __bfloat162float(h3));
    ushort4 ph = make_ushort4(*(unsigned short*)&h0, *(unsigned short*)&h1,
                              *(unsigned short*)&h2, *(unsigned short*)&h3);
    ushort4 pl = make_ushort4(*(unsigned short*)&l0, *(unsigned short*)&l1,
                              *(unsigned short*)&l2, *(unsigned short*)&l3);
    ((ushort4*)hi)[i] = ph;
    ((ushort4*)lo)[i] = pl;
    float* o = outS + i * 4;
    o[0] = v.x; o[1] = v.y; o[2] = v.z; o[3] = v.w;
}

// ---------------------------------------------------------------------------
// Kernel 2: classic-tensor-core GEMM  logits = 20 * (xh·sh + xh·sl + xl·sh)
// CTA 128x128, BK=64, 8 warps (warp tile 32x64), mma.m16n8k16 bf16.
// 2-stage cp.async pipeline, padded SMEM stride 144B (128B data + 16B pad).
// ---------------------------------------------------------------------------
#define RSTRIDE     144        // bytes per row in SMEM (128 data + 16 pad)
#define STAGE_BYTES 36864      // (A:128x144) + (B:128x144)
#define B_OFF       18432
#define SM_TOTAL    73728      // 2 stages
#define N_CHUNKS    96         // 3 passes x (2048 / 64)

__global__ __launch_bounds__(256, 2) void gemm_mma_kernel()
{
    extern __shared__ __nv_bfloat16 smem[];
    const uint32_t sbase = smem_to_u32(smem);

    const int tid  = threadIdx.x;
    const int lane = tid & 31;
    const int wid  = tid >> 5;
    const int wm   = wid & 3;        // 4 m-warps (32 rows each)
    const int wn   = wid >> 2;       // 2 n-warps (64 cols each)
    const int m0   = blockIdx.x * 128;
    const int n0   = blockIdx.y * 128;

    // cp.async mapping: tile = 128 rows x 8 x 16B; thread covers 4 rows (r0+32i)
    const int r0 = tid >> 3;                       // 0..31
    const int cb = (tid & 7) * 16;                 // byte col in row
    const int ce = (tid & 7) * 8;                  // element col

    // ldmatrix lane-invariant offsets (stride 144)
    const uint32_t a_lds = (uint32_t)((wm * 32 + (lane & 15)) * RSTRIDE + (lane >> 4) * 16);
    const uint32_t b_lds = (uint32_t)((wn * 64 + (lane & 7) + ((lane >> 3) & 1) * 8) * RSTRIDE
                                      + (lane >> 4) * 16);

    float d[2][8][4];
#pragma unroll
    for (int t = 0; t < 2; ++t)
#pragma unroll
        for (int j = 0; j < 8; ++j)
#pragma unroll
            for (int k = 0; k < 4; ++k) d[t][j][k] = 0.0f;

    auto issue = [&](int c) {
        const __nv_bfloat16 *pa, *pb;
        const int seg = c >> 5;
        if (seg == 0)      { pa = g_Ah; pb = g_Sh; }
        else if (seg == 1) { pa = g_Ah; pb = g_Sl; }
        else               { pa = g_Al; pb = g_Sh; }
        const int kk = (c & 31) << 6;   // *64
        const uint32_t ab = sbase + (uint32_t)(c & 1) * STAGE_BYTES;
        const uint32_t bb = ab + B_OFF;
#pragma unroll
        for (int i = 0; i < 4; ++i) {
            const int r = r0 + 32 * i;
            cp_async16(ab + r * RSTRIDE + cb, pa + (size_t)(m0 + r) * D_DIM + kk + ce);
            cp_async16(bb + r * RSTRIDE + cb, pb + (size_t)(n0 + r) * D_DIM + kk + ce);
        }
        asm volatile("cp.async.commit_group;");
    };

    issue(0);

    for (int c = 0; c < N_CHUNKS; ++c) {
        // prefetch next chunk FIRST (overlaps wait), then wait for group c
        if (c + 1 < N_CHUNKS) {
            issue(c + 1);
            asm volatile("cp.async.wait_group 1;");
        } else {
            asm volatile("cp.async.wait_group 0;");
        }
        __syncthreads();

        const uint32_t abase = sbase + (uint32_t)(c & 1) * STAGE_BYTES;
        const uint32_t bbase = abase + B_OFF;

#pragma unroll
        for (int ks = 0; ks < 4; ++ks) {
            uint32_t a[2][4];
#pragma unroll
            for (int t = 0; t < 2; ++t)
                ldsm_x4(a[t][0], a[t][1], a[t][2], a[t][3],
                        abase + a_lds + t * (16 * RSTRIDE) + ks * 32);
            uint32_t b[4][4];
#pragma unroll
            for (int j = 0; j < 4; ++j)
                ldsm_x4(b[j][0], b[j][1], b[j][2], b[j][3],
                        bbase + b_lds + j * (16 * RSTRIDE) + ks * 32);
#pragma unroll
            for (int t = 0; t < 2; ++t)
#pragma unroll
                for (int j = 0; j < 4; ++j) {
                    mma_bf16(d[t][2 * j + 0], a[t], b[j][0], b[j][2]);
                    mma_bf16(d[t][2 * j + 1], a[t], b[j][1], b[j][3]);
                }
        }
        __syncthreads();   // stage (c&1) fully consumed before issue(c+2) overwrites
    }

    // epilogue: scale by 20, store fp32 logits
#pragma unroll
    for (int t = 0; t < 2; ++t) {
        const int mrow = m0 + wm * 32 + t * 16 + (lane >> 2);
#pragma unroll
        for (int j = 0; j < 8; ++j) {
            const int col = n0 + wn * 64 + j * 8 + (lane & 3) * 2;
            float2 lo2 = make_float2(d[t][j][0] * TEMP_INV, d[t][j][1] * TEMP_INV);
            float2 hi2 = make_float2(d[t][j][2] * TEMP_INV, d[t][j][3] * TEMP_INV);
            *(float2*)(g_logits + (size_t)mrow * P_DIM + col) = lo2;
            *(float2*)(g_logits + (size_t)(mrow + 8) * P_DIM + col) = hi2;
        }
    }
}

// ---------------------------------------------------------------------------
// Kernel 3: per-row logsumexp + NLL contribution (one block per batch row)
// ---------------------------------------------------------------------------
__global__ __launch_bounds__(256) void lse_loss_kernel(float* __restrict__ loss)
{
    const int b = blockIdx.x;
    const int tid = threadIdx.x;
    const float* row = g_logits + (size_t)b * P_DIM;
    __shared__ float sh[256];

    float mx = -CUDART_INF_F;
    for (int i = tid; i < P_DIM; i += 256) mx = fmaxf(mx, row[i]);
    sh[tid] = mx; __syncthreads();
    for (int s = 128; s > 0; s >>= 1) {
        if (tid < s) sh[tid] = fmaxf(sh[tid], sh[tid + s]);
        __syncthreads();
    }
    const float m = sh[0];
    __syncthreads();

    float acc = 0.0f;
    for (int i = tid; i < P_DIM; i += 256) acc += __expf(row[i] - m);
    sh[tid] = acc; __syncthreads();
    for (int s = 128; s > 0; s >>= 1) {
        if (tid < s) sh[tid] += sh[tid + s];
        __syncthreads();
    }

    if (tid == 0) {
        float lse = m + logf(sh[0]);
        float tgt = row[g_labels[b]];
        atomicAdd(loss, (lse - tgt) * (1.0f / (float)B_DIM));
    }
}

// ---------------------------------------------------------------------------
// Kernel 4: sequential momentum-EMA scatter + renorm (first-occurrence blocks
// replay the full duplicate chain, matching the reference scan semantics)
// ---------------------------------------------------------------------------
__global__ __launch_bounds__(256) void ema_update_kernel(
    const float* __restrict__ X,
    const float* __restrict__ S,
    float* __restrict__ outS)
{
    const int b = blockIdx.x;
    const int lab = g_labels[b];

    for (int b2 = 0; b2 < b; ++b2)
        if (g_labels[b2] == lab) return;

    const int tid = threadIdx.x;
    __shared__ float sh[256];

    float r[8];
    const float* srow = S + (size_t)lab * D_DIM;
#pragma unroll
    for (int i = 0; i < 8; ++i) r[i] = srow[tid + i * 256];

    for (int b2 = b; b2 < B_DIM; ++b2) {
        if (g_labels[b2] != lab) continue;
        const float* x = X + (size_t)b2 * D_DIM;
        float ss = 0.0f;
#pragma unroll
        for (int i = 0; i < 8; ++i) {
            r[i] = MOMENTUM * r[i] + (1.0f - MOMENTUM) * x[tid + i * 256];
            ss = fmaf(r[i], r[i], ss);
        }
        sh[tid] = ss; __syncthreads();
        for (int s = 128; s > 0; s >>= 1) {
            if (tid < s) sh[tid] += sh[tid + s];
            __syncthreads();
        }
        float inv = 1.0f / sqrtf(sh[0]);
        __syncthreads();
#pragma unroll
        for (int i = 0; i < 8; ++i) r[i] *= inv;
    }

    float* orow = outS + (size_t)lab * D_DIM;
#pragma unroll
    for (int i = 0; i < 8; ++i) orow[tid + i * 256] = r[i];
}

// ---------------------------------------------------------------------------
extern "C" void kernel_launch(void* const* d_in, const int* in_sizes, int n_in,
                              void* d_out, int out_size)
{
    const float* X      = (const float*)d_in[0];
    const float* S      = (const float*)d_in[1];
    const void*  alabel = d_in[4];

    float* out  = (float*)d_out;
    float* loss = out;
    float* outS = out + 1;

    static __nv_bfloat16 *Ah_p = nullptr, *Al_p = nullptr, *Sh_p = nullptr, *Sl_p = nullptr;
    if (!Ah_p) {
        cudaGetSymbolAddress((void**)&Ah_p, g_Ah);
        cudaGetSymbolAddress((void**)&Al_p, g_Al);
        cudaGetSymbolAddress((void**)&Sh_p, g_Sh);
        cudaGetSymbolAddress((void**)&Sl_p, g_Sl);
        cudaFuncSetAttribute(gemm_mma_kernel,
                             cudaFuncAttributeMaxDynamicSharedMemorySize, SM_TOTAL);
    }

    prologue_kernel<<<1, 256>>>(alabel, loss);

    split_kernel<<<(B_DIM * D_DIM) / 1024, 256>>>(X, Ah_p, Al_p);
    split_copy_kernel<<<(P_DIM * D_DIM) / 1024, 256>>>(S, Sh_p, Sl_p, outS);

    dim3 ggrid(B_DIM / 128, P_DIM / 128);   // 8 x 128 (m-major waves)
    gemm_mma_kernel<<<ggrid, 256, SM_TOTAL>>>();

    lse_loss_kernel<<<B_DIM, 256>>>(loss);

    ema_update_kernel<<<B_DIM, 256>>>(X, S, outS);
}